// round 1
// baseline (speedup 1.0000x reference)
#include <cuda_runtime.h>

#define N_IMG 2
#define CIN   2048
#define FOUT  512
#define CCAT  4096
#define H     64
#define W     64
#define HW    4096
#define NCELL 50
#define EPSV  1e-5f
#define SLOPE 0.01f

// ---------------- device scratch ----------------
__device__ float g_poolT[N_IMG][NCELL][CIN];      // pooled feats, cell-major for coalesced dots
__device__ float g_prior[4][N_IMG][FOUT][36];     // 1x1 conv out, BN'd in place
__device__ float g_up[N_IMG][2048][HW];           // upsampled priors (cat channels 0..2047)
__device__ float g_conv[N_IMG][FOUT][HW];         // raw conv3x3 output
__device__ float g_ostat[FOUT][2];                // mean, var of conv3x3 output

__device__ __forceinline__ void cell_info(int j, int& sz, int& iy, int& ix) {
    if (j == 0)       { sz = 1; iy = 0; ix = 0; }
    else if (j < 5)   { sz = 2; int p = j - 1;  iy = p / 2; ix = p % 2; }
    else if (j < 14)  { sz = 3; int p = j - 5;  iy = p / 3; ix = p % 3; }
    else              { sz = 6; int p = j - 14; iy = p / 6; ix = p % 6; }
}

// ---------------- 1. adaptive pooling (all 4 sizes in one pass) ----------------
__global__ void pool_kernel(const float* __restrict__ feats) {
    int nc = blockIdx.x;                  // n*CIN + c
    int n = nc / CIN, c = nc % CIN;
    __shared__ float tile[HW];
    const float* src = feats + (size_t)nc * HW;
    for (int i = threadIdx.x; i < HW; i += blockDim.x) tile[i] = src[i];
    __syncthreads();
    int wid = threadIdx.x >> 5, lane = threadIdx.x & 31;
    for (int j = wid; j < NCELL; j += 8) {
        int sz, iy, ix; cell_info(j, sz, iy, ix);
        int hs = iy * H / sz, he = ((iy + 1) * H + sz - 1) / sz;
        int ws_ = ix * W / sz, we = ((ix + 1) * W + sz - 1) / sz;
        int ww = we - ws_;
        int cnt = (he - hs) * ww;
        float sum = 0.f;
        for (int t = lane; t < cnt; t += 32) {
            int r = hs + t / ww, col = ws_ + t % ww;
            sum += tile[r * W + col];
        }
        #pragma unroll
        for (int o = 16; o > 0; o >>= 1) sum += __shfl_xor_sync(0xffffffffu, sum, o);
        if (lane == 0) g_poolT[n][j][c] = sum / (float)cnt;
    }
}

// ---------------- 2. 1x1 conv on pooled grids ----------------
// grid (128, 4): 4 output channels per block, one branch per blockIdx.y
__global__ void conv1x1_kernel(const float* __restrict__ w0, const float* __restrict__ w1,
                               const float* __restrict__ w2, const float* __restrict__ w3) {
    int og = blockIdx.x, br = blockIdx.y;
    const float* wsrc = (br == 0) ? w0 : (br == 1) ? w1 : (br == 2) ? w2 : w3;
    int o0 = og * 4;
    __shared__ float sw[4][CIN];
    for (int i = threadIdx.x; i < 4 * CIN; i += 256)
        sw[i / CIN][i % CIN] = wsrc[(size_t)(o0 + i / CIN) * CIN + (i % CIN)];
    __syncthreads();
    int sz    = (br == 0) ? 1 : (br == 1) ? 2 : (br == 2) ? 3 : 6;
    int cell0 = (br == 0) ? 0 : (br == 1) ? 1 : (br == 2) ? 5 : 14;
    int pp = sz * sz;
    int np = N_IMG * pp;
    int wid = threadIdx.x >> 5, lane = threadIdx.x & 31;
    for (int j = wid; j < np; j += 8) {
        int n = j / pp, p = j % pp;
        const float* prow = &g_poolT[n][cell0 + p][0];
        float a0 = 0, a1 = 0, a2 = 0, a3 = 0;
        for (int k = lane; k < CIN; k += 32) {
            float v = prow[k];
            a0 += sw[0][k] * v; a1 += sw[1][k] * v;
            a2 += sw[2][k] * v; a3 += sw[3][k] * v;
        }
        #pragma unroll
        for (int o = 16; o > 0; o >>= 1) {
            a0 += __shfl_xor_sync(0xffffffffu, a0, o);
            a1 += __shfl_xor_sync(0xffffffffu, a1, o);
            a2 += __shfl_xor_sync(0xffffffffu, a2, o);
            a3 += __shfl_xor_sync(0xffffffffu, a3, o);
        }
        if (lane == 0) {
            g_prior[br][n][o0 + 0][p] = a0;
            g_prior[br][n][o0 + 1][p] = a1;
            g_prior[br][n][o0 + 2][p] = a2;
            g_prior[br][n][o0 + 3][p] = a3;
        }
    }
}

// ---------------- 3. per-branch BN (batch stats) + leaky relu, in place ----------------
// grid (512, 4), 32 threads
__global__ void prior_bn_kernel(const float* __restrict__ g0, const float* __restrict__ b0,
                                const float* __restrict__ g1, const float* __restrict__ b1,
                                const float* __restrict__ g2, const float* __restrict__ b2,
                                const float* __restrict__ g3, const float* __restrict__ b3) {
    int o = blockIdx.x, br = blockIdx.y;
    const float* gam = (br == 0) ? g0 : (br == 1) ? g1 : (br == 2) ? g2 : g3;
    const float* bet = (br == 0) ? b0 : (br == 1) ? b1 : (br == 2) ? b2 : b3;
    int sz = (br == 0) ? 1 : (br == 1) ? 2 : (br == 2) ? 3 : 6;
    int pp = sz * sz, cnt = N_IMG * pp;
    int lane = threadIdx.x;
    float s = 0.f, sq = 0.f;
    for (int e = lane; e < cnt; e += 32) {
        float v = g_prior[br][e / pp][o][e % pp];
        s += v; sq += v * v;
    }
    #pragma unroll
    for (int k = 16; k > 0; k >>= 1) {
        s  += __shfl_xor_sync(0xffffffffu, s, k);
        sq += __shfl_xor_sync(0xffffffffu, sq, k);
    }
    float mean = s / (float)cnt;
    float var  = sq / (float)cnt - mean * mean;
    float sc = rsqrtf(var + EPSV) * gam[o];
    float sh = bet[o] - mean * sc;
    for (int e = lane; e < cnt; e += 32) {
        float v = g_prior[br][e / pp][o][e % pp];
        v = v * sc + sh;
        g_prior[br][e / pp][o][e % pp] = (v >= 0.f) ? v : SLOPE * v;
    }
}

// ---------------- 4. bilinear upsample (align_corners=True) ----------------
__global__ void upsample_kernel() {
    int idx = blockIdx.x * 256 + threadIdx.x;      // [n][sc(2048)][py][px]
    if (idx >= N_IMG * 2048 * HW) return;
    int px = idx & 63;
    int py = (idx >> 6) & 63;
    int sc = (idx >> 12) & 2047;
    int n  = idx >> 23;
    int br = sc >> 9, o = sc & 511;
    int sz = (br == 0) ? 1 : (br == 1) ? 2 : (br == 2) ? 3 : 6;
    float scale = (float)(sz - 1) / 63.f;
    float yc = py * scale, xc = px * scale;
    int y0 = (int)floorf(yc), x0 = (int)floorf(xc);
    int y1 = min(y0 + 1, sz - 1), x1 = min(x0 + 1, sz - 1);
    float wy = yc - (float)y0, wx = xc - (float)x0;
    const float* p = &g_prior[br][n][o][0];
    float v = p[y0 * sz + x0] * (1.f - wy) * (1.f - wx)
            + p[y1 * sz + x0] * wy * (1.f - wx)
            + p[y0 * sz + x1] * (1.f - wy) * wx
            + p[y1 * sz + x1] * wy * wx;
    ((float*)g_up)[idx] = v;
}

// ---------------- 5. conv3x3 over concat(priors, feats) ----------------
// grid (64 spatial tiles, 4 cout tiles, 2 images), 256 threads.
// Block tile: 128 couts x (8x8 px). Thread tile: 8 couts x 4 px.
#define CK 8
__global__ __launch_bounds__(256) void conv3x3_kernel(const float* __restrict__ feats,
                                                      const float* __restrict__ wb) {
    int n  = blockIdx.z;
    int ot = blockIdx.y;
    int st = blockIdx.x;
    int ty0 = (st / 8) * 8, tx0 = (st % 8) * 8;
    int tid  = threadIdx.x;
    int tcol = tid & 15;       // pixel group
    int trow = tid >> 4;       // cout group (8 couts each)
    int py  = tcol >> 1, px0 = (tcol & 1) * 4;
    __shared__ float sIn[CK][10][12];
    __shared__ float sW[CK][9][128];
    float acc[8][4];
    #pragma unroll
    for (int i = 0; i < 8; i++)
        #pragma unroll
        for (int j = 0; j < 4; j++) acc[i][j] = 0.f;

    int o_load = tid >> 1;          // 0..127
    int part   = tid & 1;           // half of the 72-float run

    for (int c0 = 0; c0 < CCAT; c0 += CK) {
        const float* src = (c0 < 2048) ? &g_up[n][c0][0]
                                       : feats + ((size_t)n * CIN + (c0 - 2048)) * HW;
        // input patch CK x 10 x 10 (zero-padded)
        for (int i = tid; i < CK * 100; i += 256) {
            int c = i / 100, r = (i % 100) / 10, col = i % 10;
            int gy = ty0 + r - 1, gx = tx0 + col - 1;
            float v = 0.f;
            if (gy >= 0 && gy < H && gx >= 0 && gx < W)
                v = src[(size_t)c * HW + gy * W + gx];
            sIn[c][r][col] = v;
        }
        // weights: 128 couts x CK cin x 9 taps; each thread reads 36 contiguous floats
        {
            size_t base = ((size_t)(ot * 128 + o_load) * CCAT + c0) * 9 + part * 36;
            const float4* gsrc = (const float4*)(wb + base);
            #pragma unroll
            for (int q4 = 0; q4 < 9; q4++) {
                float4 v = gsrc[q4];
                #pragma unroll
                for (int e = 0; e < 4; e++) {
                    int q = part * 36 + q4 * 4 + e;
                    sW[q / 9][q % 9][o_load] = ((const float*)&v)[e];
                }
            }
        }
        __syncthreads();
        #pragma unroll 2
        for (int c = 0; c < CK; c++) {
            #pragma unroll
            for (int ky = 0; ky < 3; ky++) {
                float a[6];
                #pragma unroll
                for (int j = 0; j < 6; j++) a[j] = sIn[c][py + ky][px0 + j];
                #pragma unroll
                for (int kx = 0; kx < 3; kx++) {
                    float wv[8];
                    *(float4*)&wv[0] = *(const float4*)&sW[c][ky * 3 + kx][trow * 8];
                    *(float4*)&wv[4] = *(const float4*)&sW[c][ky * 3 + kx][trow * 8 + 4];
                    #pragma unroll
                    for (int i = 0; i < 8; i++)
                        #pragma unroll
                        for (int j = 0; j < 4; j++)
                            acc[i][j] += wv[i] * a[kx + j];
                }
            }
        }
        __syncthreads();
    }
    int oy = ty0 + py, ox = tx0 + px0;
    int oc0 = ot * 128 + trow * 8;
    #pragma unroll
    for (int i = 0; i < 8; i++) {
        float4 v = make_float4(acc[i][0], acc[i][1], acc[i][2], acc[i][3]);
        *(float4*)&g_conv[n][oc0 + i][oy * W + ox] = v;
    }
}

// ---------------- 6. final BN stats ----------------
__global__ void out_stats_kernel() {
    int c = blockIdx.x, tid = threadIdx.x;
    float s = 0.f, sq = 0.f;
    for (int e = tid; e < N_IMG * HW; e += 256) {
        float v = g_conv[e / HW][c][e % HW];
        s += v; sq += v * v;
    }
    __shared__ float shs[8], shq[8];
    #pragma unroll
    for (int k = 16; k > 0; k >>= 1) {
        s  += __shfl_xor_sync(0xffffffffu, s, k);
        sq += __shfl_xor_sync(0xffffffffu, sq, k);
    }
    if ((tid & 31) == 0) { shs[tid >> 5] = s; shq[tid >> 5] = sq; }
    __syncthreads();
    if (tid == 0) {
        float ts = 0.f, tq = 0.f;
        #pragma unroll
        for (int k = 0; k < 8; k++) { ts += shs[k]; tq += shq[k]; }
        float mean = ts / (float)(N_IMG * HW);
        float var  = tq / (float)(N_IMG * HW) - mean * mean;
        g_ostat[c][0] = mean;
        g_ostat[c][1] = var;
    }
}

// ---------------- 7. finalize: BN + leaky relu ----------------
__global__ void finalize_kernel(const float* __restrict__ gb, const float* __restrict__ bb,
                                float* __restrict__ out) {
    int idx = blockIdx.x * 256 + threadIdx.x;      // [n][c][hw]
    if (idx >= N_IMG * FOUT * HW) return;
    int c = (idx >> 12) & 511;
    float mean = g_ostat[c][0], var = g_ostat[c][1];
    float sc = rsqrtf(var + EPSV) * gb[c];
    float v = ((const float*)g_conv)[idx];
    v = (v - mean) * sc + bb[c];
    out[idx] = (v >= 0.f) ? v : SLOPE * v;
}

// ---------------- launch ----------------
extern "C" void kernel_launch(void* const* d_in, const int* in_sizes, int n_in,
                              void* d_out, int out_size) {
    const float* feats = (const float*)d_in[0];
    const float* w0 = (const float*)d_in[1];
    const float* g0 = (const float*)d_in[2];
    const float* b0 = (const float*)d_in[3];
    const float* w1 = (const float*)d_in[4];
    const float* g1 = (const float*)d_in[5];
    const float* b1 = (const float*)d_in[6];
    const float* w2 = (const float*)d_in[7];
    const float* g2 = (const float*)d_in[8];
    const float* b2 = (const float*)d_in[9];
    const float* w3 = (const float*)d_in[10];
    const float* g3 = (const float*)d_in[11];
    const float* b3 = (const float*)d_in[12];
    const float* wb = (const float*)d_in[13];
    const float* gb = (const float*)d_in[14];
    const float* bb = (const float*)d_in[15];

    pool_kernel<<<N_IMG * CIN, 256>>>(feats);
    conv1x1_kernel<<<dim3(128, 4), 256>>>(w0, w1, w2, w3);
    prior_bn_kernel<<<dim3(512, 4), 32>>>(g0, b0, g1, b1, g2, b2, g3, b3);
    upsample_kernel<<<(N_IMG * 2048 * HW) / 256, 256>>>();
    conv3x3_kernel<<<dim3(64, 4, 2), 256>>>(feats, wb);
    out_stats_kernel<<<FOUT, 256>>>();
    finalize_kernel<<<(N_IMG * FOUT * HW) / 256, 256>>>(gb, bb, (float*)d_out);
}

// round 3
// speedup vs baseline: 4.1700x; 4.1700x over previous
#include <cuda_runtime.h>
#include <cstdint>

#define N_IMG 2
#define CIN   2048
#define FOUT  512
#define CCAT  4096
#define H     64
#define W     64
#define HW    4096
#define NCELL 50
#define EPSV  1e-5f
#define SLOPE 0.01f

// ---------------- device scratch ----------------
__device__ float g_poolT[N_IMG][NCELL][CIN];
__device__ float g_prior[4][N_IMG][FOUT][36];
__device__ float g_inp[(size_t)N_IMG * 66 * 66 * CCAT];   // NHWC padded concat input (tf32)
__device__ float g_wt[(size_t)9 * FOUT * CCAT];           // weights [tap][o][c] (tf32)
__device__ float g_conv[N_IMG][FOUT][HW];
__device__ float g_ostat[FOUT][2];

__device__ __forceinline__ uint32_t smem_u32(const void* p) {
    uint32_t a;
    asm("{ .reg .u64 t; cvta.to.shared.u64 t, %1; cvt.u32.u64 %0, t; }" : "=r"(a) : "l"(p));
    return a;
}
__device__ __forceinline__ float to_tf32(float x) {
    uint32_t u;
    asm("cvt.rna.tf32.f32 %0, %1;" : "=r"(u) : "f"(x));
    return __uint_as_float(u);
}
__device__ __forceinline__ void cp16(uint32_t saddr, const float* gaddr) {
    asm volatile("cp.async.cg.shared.global [%0], [%1], 16;" :: "r"(saddr), "l"(gaddr));
}
#define CP_COMMIT() asm volatile("cp.async.commit_group;" ::: "memory")
#define CP_WAIT0()  asm volatile("cp.async.wait_group 0;" ::: "memory")

__device__ __forceinline__ void mma_tf32(float& c0, float& c1, float& c2, float& c3,
                                         uint32_t a0, uint32_t a1, uint32_t a2, uint32_t a3,
                                         uint32_t b0, uint32_t b1) {
    asm volatile(
        "mma.sync.aligned.m16n8k8.row.col.f32.tf32.tf32.f32 "
        "{%0,%1,%2,%3}, {%4,%5,%6,%7}, {%8,%9}, {%0,%1,%2,%3};"
        : "+f"(c0), "+f"(c1), "+f"(c2), "+f"(c3)
        : "r"(a0), "r"(a1), "r"(a2), "r"(a3), "r"(b0), "r"(b1));
}

__device__ __forceinline__ void cell_info(int j, int& sz, int& iy, int& ix) {
    if (j == 0)       { sz = 1; iy = 0; ix = 0; }
    else if (j < 5)   { sz = 2; int p = j - 1;  iy = p / 2; ix = p % 2; }
    else if (j < 14)  { sz = 3; int p = j - 5;  iy = p / 3; ix = p % 3; }
    else              { sz = 6; int p = j - 14; iy = p / 6; ix = p % 6; }
}

// ---------------- 1. adaptive pooling ----------------
__global__ void pool_kernel(const float* __restrict__ feats) {
    int nc = blockIdx.x;
    int n = nc / CIN;
    __shared__ float tile[HW];
    const float* src = feats + (size_t)nc * HW;
    for (int i = threadIdx.x; i < HW; i += blockDim.x) tile[i] = src[i];
    __syncthreads();
    int wid = threadIdx.x >> 5, lane = threadIdx.x & 31;
    int c = nc % CIN;
    for (int j = wid; j < NCELL; j += 8) {
        int sz, iy, ix; cell_info(j, sz, iy, ix);
        int hs = iy * H / sz, he = ((iy + 1) * H + sz - 1) / sz;
        int ws_ = ix * W / sz, we = ((ix + 1) * W + sz - 1) / sz;
        int ww = we - ws_;
        int cnt = (he - hs) * ww;
        float sum = 0.f;
        for (int t = lane; t < cnt; t += 32) {
            int r = hs + t / ww, col = ws_ + t % ww;
            sum += tile[r * W + col];
        }
        #pragma unroll
        for (int o = 16; o > 0; o >>= 1) sum += __shfl_xor_sync(0xffffffffu, sum, o);
        if (lane == 0) g_poolT[n][j][c] = sum / (float)cnt;
    }
}

// ---------------- 2. 1x1 conv on pooled grids ----------------
__global__ void conv1x1_kernel(const float* __restrict__ w0, const float* __restrict__ w1,
                               const float* __restrict__ w2, const float* __restrict__ w3) {
    int og = blockIdx.x, br = blockIdx.y;
    const float* wsrc = (br == 0) ? w0 : (br == 1) ? w1 : (br == 2) ? w2 : w3;
    int o0 = og * 4;
    __shared__ float sw[4][CIN];
    for (int i = threadIdx.x; i < 4 * CIN; i += 256)
        sw[i / CIN][i % CIN] = wsrc[(size_t)(o0 + i / CIN) * CIN + (i % CIN)];
    __syncthreads();
    int sz    = (br == 0) ? 1 : (br == 1) ? 2 : (br == 2) ? 3 : 6;
    int cell0 = (br == 0) ? 0 : (br == 1) ? 1 : (br == 2) ? 5 : 14;
    int pp = sz * sz;
    int np = N_IMG * pp;
    int wid = threadIdx.x >> 5, lane = threadIdx.x & 31;
    for (int j = wid; j < np; j += 8) {
        int n = j / pp, p = j % pp;
        const float* prow = &g_poolT[n][cell0 + p][0];
        float a0 = 0, a1 = 0, a2 = 0, a3 = 0;
        for (int k = lane; k < CIN; k += 32) {
            float v = prow[k];
            a0 += sw[0][k] * v; a1 += sw[1][k] * v;
            a2 += sw[2][k] * v; a3 += sw[3][k] * v;
        }
        #pragma unroll
        for (int o = 16; o > 0; o >>= 1) {
            a0 += __shfl_xor_sync(0xffffffffu, a0, o);
            a1 += __shfl_xor_sync(0xffffffffu, a1, o);
            a2 += __shfl_xor_sync(0xffffffffu, a2, o);
            a3 += __shfl_xor_sync(0xffffffffu, a3, o);
        }
        if (lane == 0) {
            g_prior[br][n][o0 + 0][p] = a0;
            g_prior[br][n][o0 + 1][p] = a1;
            g_prior[br][n][o0 + 2][p] = a2;
            g_prior[br][n][o0 + 3][p] = a3;
        }
    }
}

// ---------------- 3. per-branch BN + leaky relu ----------------
__global__ void prior_bn_kernel(const float* __restrict__ g0, const float* __restrict__ b0,
                                const float* __restrict__ g1, const float* __restrict__ b1,
                                const float* __restrict__ g2, const float* __restrict__ b2,
                                const float* __restrict__ g3, const float* __restrict__ b3) {
    int o = blockIdx.x, br = blockIdx.y;
    const float* gam = (br == 0) ? g0 : (br == 1) ? g1 : (br == 2) ? g2 : g3;
    const float* bet = (br == 0) ? b0 : (br == 1) ? b1 : (br == 2) ? b2 : b3;
    int sz = (br == 0) ? 1 : (br == 1) ? 2 : (br == 2) ? 3 : 6;
    int pp = sz * sz, cnt = N_IMG * pp;
    int lane = threadIdx.x;
    float s = 0.f, sq = 0.f;
    for (int e = lane; e < cnt; e += 32) {
        float v = g_prior[br][e / pp][o][e % pp];
        s += v; sq += v * v;
    }
    #pragma unroll
    for (int k = 16; k > 0; k >>= 1) {
        s  += __shfl_xor_sync(0xffffffffu, s, k);
        sq += __shfl_xor_sync(0xffffffffu, sq, k);
    }
    float mean = s / (float)cnt;
    float var  = sq / (float)cnt - mean * mean;
    float sc = rsqrtf(var + EPSV) * gam[o];
    float sh = bet[o] - mean * sc;
    for (int e = lane; e < cnt; e += 32) {
        float v = g_prior[br][e / pp][o][e % pp];
        v = v * sc + sh;
        g_prior[br][e / pp][o][e % pp] = (v >= 0.f) ? v : SLOPE * v;
    }
}

// ---------------- 4a. upsampled priors -> NHWC (channels 0..2047) ----------------
__global__ void nhwc_up_kernel() {
    int bid = blockIdx.x;               // [img][y][x]
    int x = bid & 63, y = (bid >> 6) & 63, img = bid >> 12;
    float* dst = g_inp + ((size_t)(img * 66 + y + 1) * 66 + x + 1) * CCAT;
    for (int c = threadIdx.x; c < 2048; c += 256) {
        int br = c >> 9, o = c & 511;
        int sz = (br == 0) ? 1 : (br == 1) ? 2 : (br == 2) ? 3 : 6;
        float scale = (float)(sz - 1) / 63.f;
        float yc = y * scale, xc = x * scale;
        int y0 = (int)floorf(yc), x0 = (int)floorf(xc);
        int y1 = min(y0 + 1, sz - 1), x1 = min(x0 + 1, sz - 1);
        float wy = yc - (float)y0, wx = xc - (float)x0;
        const float* p = &g_prior[br][img][o][0];
        float v = p[y0 * sz + x0] * (1.f - wy) * (1.f - wx)
                + p[y1 * sz + x0] * wy * (1.f - wx)
                + p[y0 * sz + x1] * (1.f - wy) * wx
                + p[y1 * sz + x1] * wy * wx;
        dst[c] = to_tf32(v);
    }
}

// ---------------- 4b. feats NCHW -> NHWC (channels 2048..4095) ----------------
__global__ void nhwc_feat_kernel(const float* __restrict__ feats) {
    int bid = blockIdx.x;
    int cc = bid & 15, xc = (bid >> 4) & 1, y = (bid >> 5) & 63, img = bid >> 11;
    int c0 = cc * 128, x0 = xc * 32;
    __shared__ float t[128][33];
    int tid = threadIdx.x;
    int cr = tid >> 5, xi = tid & 31;
    #pragma unroll
    for (int s = 0; s < 16; s++) {
        int c = cr + s * 8;
        t[c][xi] = feats[((size_t)(img * CIN + c0 + c)) * HW + y * W + x0 + xi];
    }
    __syncthreads();
    int w = tid >> 5, lane = tid & 31;
    #pragma unroll
    for (int s = 0; s < 4; s++) {
        int x = w + s * 8;
        float* dst = g_inp + ((size_t)(img * 66 + y + 1) * 66 + x0 + x + 1) * CCAT + 2048 + c0;
        #pragma unroll
        for (int kk = 0; kk < 4; kk++)
            dst[lane + 32 * kk] = to_tf32(t[lane + 32 * kk][x]);
    }
}

// ---------------- 4c. zero padded borders ----------------
__global__ void border_kernel() {
    int bid = blockIdx.x;
    int img = bid / 260, b = bid % 260;
    int y, x;
    if (b < 66)       { y = 0;  x = b; }
    else if (b < 132) { y = 65; x = b - 66; }
    else if (b < 196) { y = b - 132 + 1; x = 0; }
    else              { y = b - 196 + 1; x = 65; }
    float* dst = g_inp + ((size_t)(img * 66 + y) * 66 + x) * CCAT;
    for (int c = threadIdx.x; c < CCAT; c += 256) dst[c] = 0.f;
}

// ---------------- 4d. weight transform [o][c][tap] -> [tap][o][c] ----------------
__global__ void wt_kernel(const float* __restrict__ wb) {
    int bid = blockIdx.x;               // [o(512)][cc(8)]
    int o = bid >> 3, cc = bid & 7, c0 = cc * 512;
    __shared__ float t[512 * 9];
    const float* src = wb + ((size_t)o * CCAT + c0) * 9;
    for (int i = threadIdx.x; i < 512 * 9; i += 256) t[i] = src[i];
    __syncthreads();
    for (int tap = 0; tap < 9; tap++) {
        float* dst = g_wt + ((size_t)(tap * FOUT + o)) * CCAT + c0;
        for (int c = threadIdx.x; c < 512; c += 256)
            dst[c] = to_tf32(t[c * 9 + tap]);
    }
}

// ---------------- 5. mma.sync tf32 GEMM: conv3x3 ----------------
// CTA tile: M=256 couts x N=128 px, K chunk 32. 8 warps, warp tile 64x64.
// smem stage: A [256][36], B [128][36] floats (pad 4 for bank-conflict-free frags)
#define NK 1152
#define A_STG (256 * 36)
#define B_STG (128 * 36)
#define STG   (A_STG + B_STG)
#define GEMM_SMEM (2 * STG * 4)

__global__ void __launch_bounds__(256, 1) gemm_kernel() {
    extern __shared__ __align__(16) float smem[];
    int tid = threadIdx.x;
    int lane = tid & 31, wid = tid >> 5;
    int n_tile = blockIdx.x;            // 0..63
    int m_tile = blockIdx.y;            // 0..1
    int img = n_tile >> 5;
    int rb  = n_tile & 31;
    int y0 = rb * 2, pix0 = rb * 128;
    int oc0 = m_tile * 256;

    int wm = wid & 3, wn = wid >> 2;    // warp grid 4(m) x 2(n)
    int m0 = wm * 64, n0 = wn * 64;
    int g = lane >> 2, cq = lane & 3;

    uint32_t sbase = smem_u32(smem);

    // per-thread cp.async targets
    int ar = tid >> 3, aq = tid & 7;    // A: rows ar, ar+32*j ; 16B col aq
    // B: n = (tid + 256*j)>>3 for j<4
    size_t bpix[4];
    #pragma unroll
    for (int j = 0; j < 4; j++) {
        int n = (tid + 256 * j) >> 3;
        int rr = n >> 6, x = n & 63;
        bpix[j] = ((size_t)(img * 66 + y0 + rr) * 66 + x);
    }

    float acc[4][8][4];
    #pragma unroll
    for (int mt = 0; mt < 4; mt++)
        #pragma unroll
        for (int nt = 0; nt < 8; nt++)
            #pragma unroll
            for (int e = 0; e < 4; e++) acc[mt][nt][e] = 0.f;

    // ---- async load of chunk k into stage s ----
    auto load_chunk = [&](int k, int s) {
        int tap = k >> 7;
        int c0 = (k & 127) << 5;
        int ky = tap / 3, kx = tap % 3;
        const float* wsrc = g_wt + ((size_t)(tap * FOUT + oc0)) * CCAT + c0;
        uint32_t sa = sbase + (uint32_t)(s * STG) * 4;
        #pragma unroll
        for (int j = 0; j < 8; j++) {
            int r = ar + 32 * j;
            cp16(sa + (uint32_t)(r * 36 + aq * 4) * 4, wsrc + (size_t)r * CCAT + aq * 4);
        }
        uint32_t sb = sa + A_STG * 4;
        size_t toff = ((size_t)ky * 66 + kx) * CCAT + c0;
        #pragma unroll
        for (int j = 0; j < 4; j++) {
            int n = (tid + 256 * j) >> 3;
            cp16(sb + (uint32_t)(n * 36 + aq * 4) * 4, g_inp + bpix[j] * CCAT + toff + aq * 4);
        }
        CP_COMMIT();
    };

    load_chunk(0, 0);
    CP_WAIT0();
    __syncthreads();

    for (int k = 0; k < NK; k++) {
        int cur = k & 1;
        if (k + 1 < NK) load_chunk(k + 1, cur ^ 1);

        const float* sA = smem + cur * STG;
        const float* sB = sA + A_STG;
        #pragma unroll
        for (int k8 = 0; k8 < 4; k8++) {
            int k0 = k8 * 8;
            uint32_t a[4][4], b[8][2];
            #pragma unroll
            for (int mt = 0; mt < 4; mt++) {
                int row = m0 + mt * 16 + g;
                a[mt][0] = __float_as_uint(sA[row * 36 + k0 + cq]);
                a[mt][1] = __float_as_uint(sA[(row + 8) * 36 + k0 + cq]);
                a[mt][2] = __float_as_uint(sA[row * 36 + k0 + cq + 4]);
                a[mt][3] = __float_as_uint(sA[(row + 8) * 36 + k0 + cq + 4]);
            }
            #pragma unroll
            for (int nt = 0; nt < 8; nt++) {
                int col = n0 + nt * 8 + g;
                b[nt][0] = __float_as_uint(sB[col * 36 + k0 + cq]);
                b[nt][1] = __float_as_uint(sB[col * 36 + k0 + cq + 4]);
            }
            #pragma unroll
            for (int mt = 0; mt < 4; mt++)
                #pragma unroll
                for (int nt = 0; nt < 8; nt++)
                    mma_tf32(acc[mt][nt][0], acc[mt][nt][1], acc[mt][nt][2], acc[mt][nt][3],
                             a[mt][0], a[mt][1], a[mt][2], a[mt][3], b[nt][0], b[nt][1]);
        }
        CP_WAIT0();
        __syncthreads();
    }

    // epilogue: write to g_conv
    #pragma unroll
    for (int mt = 0; mt < 4; mt++) {
        int row = m0 + mt * 16 + g;
        #pragma unroll
        for (int nt = 0; nt < 8; nt++) {
            int col = pix0 + n0 + nt * 8 + 2 * cq;
            *(float2*)&g_conv[img][oc0 + row][col]     = make_float2(acc[mt][nt][0], acc[mt][nt][1]);
            *(float2*)&g_conv[img][oc0 + row + 8][col] = make_float2(acc[mt][nt][2], acc[mt][nt][3]);
        }
    }
}

// ---------------- 6. final BN stats ----------------
__global__ void out_stats_kernel() {
    int c = blockIdx.x, tid = threadIdx.x;
    float s = 0.f, sq = 0.f;
    for (int e = tid; e < N_IMG * HW; e += 256) {
        float v = g_conv[e / HW][c][e % HW];
        s += v; sq += v * v;
    }
    __shared__ float shs[8], shq[8];
    #pragma unroll
    for (int k = 16; k > 0; k >>= 1) {
        s  += __shfl_xor_sync(0xffffffffu, s, k);
        sq += __shfl_xor_sync(0xffffffffu, sq, k);
    }
    if ((tid & 31) == 0) { shs[tid >> 5] = s; shq[tid >> 5] = sq; }
    __syncthreads();
    if (tid == 0) {
        float ts = 0.f, tq = 0.f;
        #pragma unroll
        for (int k = 0; k < 8; k++) { ts += shs[k]; tq += shq[k]; }
        float mean = ts / (float)(N_IMG * HW);
        float var  = tq / (float)(N_IMG * HW) - mean * mean;
        g_ostat[c][0] = mean;
        g_ostat[c][1] = var;
    }
}

// ---------------- 7. finalize: BN + leaky relu ----------------
__global__ void finalize_kernel(const float* __restrict__ gb, const float* __restrict__ bb,
                                float* __restrict__ out) {
    int idx = blockIdx.x * 256 + threadIdx.x;
    if (idx >= N_IMG * FOUT * HW) return;
    int c = (idx >> 12) & 511;
    float mean = g_ostat[c][0], var = g_ostat[c][1];
    float sc = rsqrtf(var + EPSV) * gb[c];
    float v = ((const float*)g_conv)[idx];
    v = (v - mean) * sc + bb[c];
    out[idx] = (v >= 0.f) ? v : SLOPE * v;
}

// ---------------- launch ----------------
extern "C" void kernel_launch(void* const* d_in, const int* in_sizes, int n_in,
                              void* d_out, int out_size) {
    const float* feats = (const float*)d_in[0];
    const float* w0 = (const float*)d_in[1];
    const float* g0 = (const float*)d_in[2];
    const float* b0 = (const float*)d_in[3];
    const float* w1 = (const float*)d_in[4];
    const float* g1 = (const float*)d_in[5];
    const float* b1 = (const float*)d_in[6];
    const float* w2 = (const float*)d_in[7];
    const float* g2 = (const float*)d_in[8];
    const float* b2 = (const float*)d_in[9];
    const float* w3 = (const float*)d_in[10];
    const float* g3 = (const float*)d_in[11];
    const float* b3 = (const float*)d_in[12];
    const float* wb = (const float*)d_in[13];
    const float* gb = (const float*)d_in[14];
    const float* bb = (const float*)d_in[15];

    static int smem_set = 0;
    if (!smem_set) {
        cudaFuncSetAttribute(gemm_kernel, cudaFuncAttributeMaxDynamicSharedMemorySize, GEMM_SMEM);
        smem_set = 1;
    }

    pool_kernel<<<N_IMG * CIN, 256>>>(feats);
    conv1x1_kernel<<<dim3(128, 4), 256>>>(w0, w1, w2, w3);
    prior_bn_kernel<<<dim3(512, 4), 32>>>(g0, b0, g1, b1, g2, b2, g3, b3);
    nhwc_up_kernel<<<N_IMG * HW, 256>>>();
    nhwc_feat_kernel<<<4096, 256>>>(feats);
    border_kernel<<<N_IMG * 260, 256>>>();
    wt_kernel<<<4096, 256>>>(wb);
    gemm_kernel<<<dim3(64, 2), 256, GEMM_SMEM>>>();
    out_stats_kernel<<<FOUT, 256>>>();
    finalize_kernel<<<(N_IMG * FOUT * HW) / 256, 256>>>(gb, bb, (float*)d_out);
}